// round 16
// baseline (speedup 1.0000x reference)
#include <cuda_runtime.h>
#include <cuda_bf16.h>
#include <cstdint>
#include <math.h>

// Problem constants
#define BATCH 2
#define SEQ   2048
#define DIM   2048
#define NH    32
#define NKV   8
#define HD    64
#define KVD   (NKV*HD)    // 512
#define MTOT  (BATCH*SEQ) // 4096

// Scratch (device globals: allocation-free) — all pre-split bf16 pairs
__device__ __nv_bfloat16 g_xh [MTOT * DIM],  g_xl [MTOT * DIM];
__device__ __nv_bfloat16 g_wqh[DIM * DIM],   g_wql[DIM * DIM];
__device__ __nv_bfloat16 g_wkh[KVD * DIM],   g_wkl[KVD * DIM];
__device__ __nv_bfloat16 g_wvh[KVD * DIM],   g_wvl[KVD * DIM];
__device__ __nv_bfloat16 g_woh[DIM * DIM],   g_wol[DIM * DIM];
__device__ __nv_bfloat16 g_Qh [MTOT * DIM],  g_Ql [MTOT * DIM];
__device__ __nv_bfloat16 g_Kh [MTOT * KVD],  g_Kl [MTOT * KVD];
__device__ __nv_bfloat16 g_Vh [MTOT * KVD],  g_Vl [MTOT * KVD];
__device__ __nv_bfloat16 g_Oh [MTOT * DIM],  g_Ol [MTOT * DIM];

// ============================ helpers ======================================
__device__ __forceinline__ uint32_t smem_u32(const void* p) {
    uint32_t a;
    asm("{ .reg .u64 t; cvta.to.shared.u64 t, %1; cvt.u32.u64 %0, t; }"
        : "=r"(a) : "l"(p));
    return a;
}
__device__ __forceinline__ void cp16(uint32_t dst, const void* src) {
    asm volatile("cp.async.cg.shared.global [%0], [%1], 16;"
                 :: "r"(dst), "l"(src) : "memory");
}
#define CP_COMMIT() asm volatile("cp.async.commit_group;" ::: "memory")
#define CP_WAIT0()  asm volatile("cp.async.wait_group 0;" ::: "memory")
#define CP_WAIT1()  asm volatile("cp.async.wait_group 1;" ::: "memory")

__device__ __forceinline__ void ldmatrix_x4(uint32_t& r0, uint32_t& r1,
                                            uint32_t& r2, uint32_t& r3,
                                            uint32_t addr) {
    asm volatile("ldmatrix.sync.aligned.m8n8.x4.shared.b16 {%0,%1,%2,%3}, [%4];"
                 : "=r"(r0), "=r"(r1), "=r"(r2), "=r"(r3) : "r"(addr));
}
__device__ __forceinline__ void ldmatrix_x4_trans(uint32_t& r0, uint32_t& r1,
                                                  uint32_t& r2, uint32_t& r3,
                                                  uint32_t addr) {
    asm volatile("ldmatrix.sync.aligned.m8n8.x4.trans.shared.b16 {%0,%1,%2,%3}, [%4];"
                 : "=r"(r0), "=r"(r1), "=r"(r2), "=r"(r3) : "r"(addr));
}
__device__ __forceinline__ void mma_bf16(float* d, const uint32_t* a,
                                         const uint32_t* b) {
    asm volatile(
        "mma.sync.aligned.m16n8k16.row.col.f32.bf16.bf16.f32 "
        "{%0,%1,%2,%3}, {%4,%5,%6,%7}, {%8,%9}, {%0,%1,%2,%3};"
        : "+f"(d[0]), "+f"(d[1]), "+f"(d[2]), "+f"(d[3])
        : "r"(a[0]), "r"(a[1]), "r"(a[2]), "r"(a[3]), "r"(b[0]), "r"(b[1]));
}

// fp32 pair -> packed (hi,lo) bf16x2
__device__ __forceinline__ void split2(float a, float b, uint32_t& hi, uint32_t& lo) {
    __nv_bfloat16 ha = __float2bfloat16(a), hb = __float2bfloat16(b);
    hi = (uint32_t)__bfloat16_as_ushort(ha) |
         ((uint32_t)__bfloat16_as_ushort(hb) << 16);
    float ra = a - __bfloat162float(ha);
    float rb = b - __bfloat162float(hb);
    uint32_t d;
    asm("cvt.rn.bf16x2.f32 %0, %1, %2;" : "=r"(d) : "f"(rb), "f"(ra));
    lo = d;
}

// Fixed-shift softmax exponential: exp(s*0.125 - 46*ln2) = 2^(s*0.1803 - 46).
__device__ __forceinline__ float fexp2s(float x) {
    float y = fmaxf(fmaf(x, 0.1803368801f, -46.0f), -126.f);
    float r = rintf(y);
    float f = y - r;
    float p = 1.3333558e-3f;
    p = fmaf(p, f, 9.6181291e-3f);
    p = fmaf(p, f, 5.5504109e-2f);
    p = fmaf(p, f, 2.4022651e-1f);
    p = fmaf(p, f, 6.9314718e-1f);
    p = fmaf(p, f, 1.0f);
    return p * __int_as_float(((int)r + 127) << 23);
}

// XOR swizzle for 64B-wide rows (bijective; store & load use same map)
__device__ __forceinline__ uint32_t swz(uint32_t off) {
    return off ^ (((off >> 6) & 7u) << 4);
}

// ================ fused pre-split kernel (fp32 -> hi/lo bf16) ==============
#define SPLIT_N4 4718592
__global__ __launch_bounds__(256)
void split_all(const float* __restrict__ x,  const float* __restrict__ wq,
               const float* __restrict__ wk, const float* __restrict__ wv,
               const float* __restrict__ wo,
               __nv_bfloat16* xh,  __nv_bfloat16* xl,
               __nv_bfloat16* wqh, __nv_bfloat16* wql,
               __nv_bfloat16* wkh, __nv_bfloat16* wkl,
               __nv_bfloat16* wvh, __nv_bfloat16* wvl,
               __nv_bfloat16* woh, __nv_bfloat16* wol)
{
    int base = blockIdx.x * 512 + threadIdx.x;
#pragma unroll
    for (int u = 0; u < 2; u++) {
        int i = base + u * 256;
        if (i >= SPLIT_N4) return;
        const float* in; __nv_bfloat16 *hi, *lo; int off;
        if (i < 2097152)      { in = x;  hi = xh;  lo = xl;  off = 0; }
        else if (i < 3145728) { in = wq; hi = wqh; lo = wql; off = 2097152; }
        else if (i < 3407872) { in = wk; hi = wkh; lo = wkl; off = 3145728; }
        else if (i < 3670016) { in = wv; hi = wvh; lo = wvl; off = 3407872; }
        else                  { in = wo; hi = woh; lo = wol; off = 3670016; }
        int k = i - off;
        float4 v = ((const float4*)in)[k];
        uint32_t h0, l0, h1, l1;
        split2(v.x, v.y, h0, l0);
        split2(v.z, v.w, h1, l1);
        ((uint2*)hi)[k] = make_uint2(h0, h1);
        ((uint2*)lo)[k] = make_uint2(l0, l1);
    }
}

// ============== pre-split bf16 GEMM: swizzled 3-stage (round-8 config) =====
#define GSTG 32768
#define GEMM_SMEM (3 * GSTG)   // 98304 bytes

template<int SPLIT>
__device__ __forceinline__ void gemm_tile(
    const __nv_bfloat16* __restrict__ Ah_t, const __nv_bfloat16* __restrict__ Al_t,
    const __nv_bfloat16* __restrict__ Bh_t, const __nv_bfloat16* __restrict__ Bl_t,
    float* __restrict__ C, __nv_bfloat16* __restrict__ Ch,
    __nv_bfloat16* __restrict__ Cl, int ldc, int K, __nv_bfloat16* gsm)
{
    const uint32_t usm = smem_u32(gsm);
    const int tid  = threadIdx.x;
    const int lane = tid & 31;
    const int wid  = tid >> 5;
    const int wm   = wid & 1;
    const int wn   = wid >> 1;

    const __nv_bfloat16* srcs[4] = { Ah_t, Al_t, Bh_t, Bl_t };

    float acc[4][4][4];
#pragma unroll
    for (int i = 0; i < 4; i++)
#pragma unroll
        for (int j = 0; j < 4; j++)
#pragma unroll
            for (int q = 0; q < 4; q++) acc[i][j][q] = 0.f;

    const int aRow = wm * 64 + (lane & 15);
    const int aCol = (lane >> 4) << 4;                 // bytes
    const int bRow = wn * 32 + ((lane >> 4) << 3) + (lane & 7);
    const int bCol = ((lane >> 3) & 1) << 4;           // bytes

    const int NC = K / 32;

    auto issue = [&](int k0, uint32_t base) {
#pragma unroll
        for (int j = 0; j < 8; j++) {
            int s   = tid + (j << 8);
            int arr = s >> 9;
            int w5  = s & 511;
            int r   = w5 >> 2;
            int c8  = w5 & 3;
            cp16(base + (uint32_t)(arr * 8192) + swz((uint32_t)(r * 64 + c8 * 16)),
                 srcs[arr] + (size_t)r * K + k0 + c8 * 8);
        }
    };

    issue(0, usm);         CP_COMMIT();
    issue(32, usm + GSTG); CP_COMMIT();

    for (int c = 0; c < NC; c++) {
        CP_WAIT1();
        __syncthreads();
        if (c + 2 < NC)
            issue((c + 2) * 32, usm + (uint32_t)(((c + 2) % 3) * GSTG));
        CP_COMMIT();

        const uint32_t sb = usm + (uint32_t)((c % 3) * GSTG);
#pragma unroll
        for (int kk = 0; kk < 2; kk++) {
            const int kc = kk * 32;
            uint32_t bh[4][2], bl[4][2];
#pragma unroll
            for (int g = 0; g < 2; g++) {
                uint32_t off = swz((uint32_t)((bRow + g * 16) * 64 + bCol + kc));
                ldmatrix_x4(bh[g*2][0], bh[g*2][1], bh[g*2+1][0], bh[g*2+1][1],
                            sb + 16384 + off);
                ldmatrix_x4(bl[g*2][0], bl[g*2][1], bl[g*2+1][0], bl[g*2+1][1],
                            sb + 24576 + off);
            }
#pragma unroll
            for (int mi = 0; mi < 4; mi++) {
                uint32_t ah[4], al[4];
                uint32_t off = swz((uint32_t)((aRow + mi * 16) * 64 + aCol + kc));
                ldmatrix_x4(ah[0], ah[1], ah[2], ah[3], sb + off);
                ldmatrix_x4(al[0], al[1], al[2], al[3], sb + 8192 + off);
#pragma unroll
                for (int ni = 0; ni < 4; ni++) mma_bf16(acc[mi][ni], ah, bh[ni]);
#pragma unroll
                for (int ni = 0; ni < 4; ni++) mma_bf16(acc[mi][ni], ah, bl[ni]);
#pragma unroll
                for (int ni = 0; ni < 4; ni++) mma_bf16(acc[mi][ni], al, bh[ni]);
            }
        }
    }

    const int erow = lane >> 2;
    const int ecol = (lane & 3) << 1;
#pragma unroll
    for (int mi = 0; mi < 4; mi++) {
#pragma unroll
        for (int ni = 0; ni < 4; ni++) {
            int r0 = wm * 64 + mi * 16 + erow;
            int cc = wn * 32 + ni * 8 + ecol;
            if (SPLIT) {
                uint32_t h0, l0, h1, l1;
                split2(acc[mi][ni][0], acc[mi][ni][1], h0, l0);
                split2(acc[mi][ni][2], acc[mi][ni][3], h1, l1);
                size_t i0 = ((size_t)r0 * ldc + cc) >> 1;
                size_t i1 = ((size_t)(r0 + 8) * ldc + cc) >> 1;
                ((uint32_t*)Ch)[i0] = h0; ((uint32_t*)Cl)[i0] = l0;
                ((uint32_t*)Ch)[i1] = h1; ((uint32_t*)Cl)[i1] = l1;
            } else {
                *(float2*)&C[(size_t)r0 * ldc + cc] =
                    make_float2(acc[mi][ni][0], acc[mi][ni][1]);
                *(float2*)&C[(size_t)(r0 + 8) * ldc + cc] =
                    make_float2(acc[mi][ni][2], acc[mi][ni][3]);
            }
        }
    }
}

// Fused Q/K/V projection: grid.x = 24 n-tiles (16 Q | 4 K | 4 V)
__global__ __launch_bounds__(256, 2)
void gemm_qkv(const __nv_bfloat16* __restrict__ xh, const __nv_bfloat16* __restrict__ xl,
              const __nv_bfloat16* __restrict__ wqh, const __nv_bfloat16* __restrict__ wql,
              const __nv_bfloat16* __restrict__ wkh, const __nv_bfloat16* __restrict__ wkl,
              const __nv_bfloat16* __restrict__ wvh, const __nv_bfloat16* __restrict__ wvl,
              __nv_bfloat16* __restrict__ Qh, __nv_bfloat16* __restrict__ Ql,
              __nv_bfloat16* __restrict__ Kh, __nv_bfloat16* __restrict__ Kl,
              __nv_bfloat16* __restrict__ Vh, __nv_bfloat16* __restrict__ Vl)
{
    extern __shared__ __nv_bfloat16 gsm[];
    const int nt = blockIdx.x;
    const int bm = blockIdx.y * 128;
    const __nv_bfloat16 *Bh, *Bl;
    __nv_bfloat16 *Ch, *Cl;
    int ldc, bn;
    if (nt < 16)      { Bh = wqh; Bl = wql; Ch = Qh; Cl = Ql; ldc = DIM; bn = nt * 128; }
    else if (nt < 20) { Bh = wkh; Bl = wkl; Ch = Kh; Cl = Kl; ldc = KVD; bn = (nt - 16) * 128; }
    else              { Bh = wvh; Bl = wvl; Ch = Vh; Cl = Vl; ldc = KVD; bn = (nt - 20) * 128; }
    gemm_tile<1>(xh + (size_t)bm * DIM, xl + (size_t)bm * DIM,
                 Bh + (size_t)bn * DIM, Bl + (size_t)bn * DIM,
                 nullptr,
                 Ch + (size_t)bm * ldc + bn, Cl + (size_t)bm * ldc + bn,
                 ldc, DIM, gsm);
}

__global__ __launch_bounds__(256, 2)
void gemm_o(const __nv_bfloat16* __restrict__ Ah, const __nv_bfloat16* __restrict__ Al,
            const __nv_bfloat16* __restrict__ Bh, const __nv_bfloat16* __restrict__ Bl,
            float* __restrict__ C)
{
    extern __shared__ __nv_bfloat16 gsm[];
    const int bm = blockIdx.y * 128, bn = blockIdx.x * 128;
    gemm_tile<0>(Ah + (size_t)bm * DIM, Al + (size_t)bm * DIM,
                 Bh + (size_t)bn * DIM, Bl + (size_t)bn * DIM,
                 C + (size_t)bm * DIM + bn, nullptr, nullptr,
                 DIM, DIM, gsm);
}

// ===== Flash attention: 128q x 64kv tiles, fixed-shift softmax, 2 CTAs/SM ==
#define LDQ 72
// elems: Q hi+lo 18432 | 2 KV stages x (Kh,Kl,Vh,Vl @ 64*72=4608 each) 18432
#define AKV1 18432
#define ATT_SMEM ((18432 + 2 * AKV1) * 2)   // 110592 bytes

__global__ __launch_bounds__(256, 2)
void attn_ps(const __nv_bfloat16* __restrict__ Qh_g, const __nv_bfloat16* __restrict__ Ql_g,
             const __nv_bfloat16* __restrict__ Kh_g, const __nv_bfloat16* __restrict__ Kl_g,
             const __nv_bfloat16* __restrict__ Vh_g, const __nv_bfloat16* __restrict__ Vl_g,
             __nv_bfloat16* __restrict__ Oh, __nv_bfloat16* __restrict__ Ol)
{
    extern __shared__ __nv_bfloat16 sm[];
    const uint32_t usm = smem_u32(sm);

    const int b = blockIdx.z, h = blockIdx.y;
    const int qt = (int)gridDim.x - 1 - (int)blockIdx.x;   // heavy tiles first
    const int tid = threadIdx.x, lane = tid & 31, w = tid >> 5;
    const int kvh = h >> 2;
    const int qBase = qt * 128;
    const int wq0 = qBase + 16 * w;

    const __nv_bfloat16* kvsrc[4] = {
        Kh_g + (size_t)(b * SEQ) * KVD + kvh * HD,
        Kl_g + (size_t)(b * SEQ) * KVD + kvh * HD,
        Vh_g + (size_t)(b * SEQ) * KVD + kvh * HD,
        Vl_g + (size_t)(b * SEQ) * KVD + kvh * HD };

    {
        const __nv_bfloat16* qs[2] = {
            Qh_g + (size_t)(b * SEQ + qBase) * DIM + h * HD,
            Ql_g + (size_t)(b * SEQ + qBase) * DIM + h * HD };
#pragma unroll
        for (int j = 0; j < 8; j++) {
            int s = tid + (j << 8);
            int arr = s >> 10, r = (s >> 3) & 127, c = s & 7;
            cp16(usm + (uint32_t)((arr * 9216 + r * LDQ + c * 8) * 2),
                 qs[arr] + (size_t)r * DIM + c * 8);
        }
        CP_COMMIT();
    }

    // KV tile: 64 rows x 64 dims, 4 arrays -> 2048 chunks (8/thread)
    auto issue_kv = [&](int j, int st) {
        int kvBase = j * 64;
        uint32_t base = usm + (uint32_t)((18432 + st * AKV1) * 2);
#pragma unroll
        for (int q = 0; q < 8; q++) {
            int s = tid + (q << 8);
            int arr = s >> 9, r = (s >> 3) & 63, c = s & 7;
            cp16(base + (uint32_t)((arr * 4608 + r * LDQ + c * 8) * 2),
                 kvsrc[arr] + (size_t)(kvBase + r) * KVD + c * 8);
        }
    };

    const int ntiles = 2 * qt + 2;
    issue_kv(0, 0);
    CP_COMMIT();

    CP_WAIT1();
    __syncthreads();

    uint32_t qh[4][4], ql[4][4];
    {
        int off0 = (16*w + (lane & 15)) * LDQ + ((lane >> 4) << 3);
#pragma unroll
        for (int kb = 0; kb < 4; kb++) {
            uint32_t off = (uint32_t)((off0 + kb * 16) * 2);
            ldmatrix_x4(qh[kb][0], qh[kb][1], qh[kb][2], qh[kb][3], usm + off);
            ldmatrix_x4(ql[kb][0], ql[kb][1], ql[kb][2], ql[kb][3],
                        usm + (uint32_t)(9216 * 2) + off);
        }
    }

    float o[8][4];
#pragma unroll
    for (int nb = 0; nb < 8; nb++)
#pragma unroll
        for (int q = 0; q < 4; q++) o[nb][q] = 0.f;
    float l0 = 0.f, l1 = 0.f;

    const int bN = ((lane >> 4) << 3) + (lane & 7);
    const int bK = ((lane >> 3) & 1) << 3;
    const int vRow = lane & 15, vCol = (lane >> 4) << 3;
    const int r0   = lane >> 2;
    const int c2   = (lane & 3) << 1;
    const int qi0  = wq0 + r0, qi1 = qi0 + 8;

    for (int j = 0; j < ntiles; j++) {
        const int kvBase = j * 64;
        const int st = j & 1;
        if (j + 1 < ntiles) {
            issue_kv(j + 1, st ^ 1);
            CP_COMMIT();
            CP_WAIT1();
        } else {
            CP_WAIT0();
        }
        __syncthreads();

        if (kvBase <= wq0 + 15) {
            const uint32_t kvb = usm + (uint32_t)((18432 + st * AKV1) * 2);
            const uint32_t uKh = kvb, uKl = kvb + 4608 * 2;
            const uint32_t uVh = kvb + 9216 * 2, uVl = kvb + 13824 * 2;

            // ---- S = Q K^T (8 n-blocks) ----
            float sa[8][4];
#pragma unroll
            for (int nb = 0; nb < 8; nb++)
#pragma unroll
                for (int q = 0; q < 4; q++) sa[nb][q] = 0.f;

#pragma unroll
            for (int kb = 0; kb < 4; kb++) {
                uint32_t bhf[8][2], blf[8][2];
#pragma unroll
                for (int g = 0; g < 4; g++) {
                    uint32_t off = (uint32_t)(((g*16 + bN) * LDQ + kb*16 + bK) * 2);
                    ldmatrix_x4(bhf[2*g][0], bhf[2*g][1],
                                bhf[2*g+1][0], bhf[2*g+1][1], uKh + off);
                    ldmatrix_x4(blf[2*g][0], blf[2*g][1],
                                blf[2*g+1][0], blf[2*g+1][1], uKl + off);
                }
#pragma unroll
                for (int nb = 0; nb < 8; nb++) mma_bf16(sa[nb], qh[kb], bhf[nb]);
#pragma unroll
                for (int nb = 0; nb < 8; nb++) mma_bf16(sa[nb], qh[kb], blf[nb]);
#pragma unroll
                for (int nb = 0; nb < 8; nb++) mma_bf16(sa[nb], ql[kb], bhf[nb]);
            }

            // ---- causal mask (boundary tile only) ----
            if (kvBase + 63 > wq0) {
#pragma unroll
                for (int nb = 0; nb < 8; nb++) {
                    int col = kvBase + nb * 8 + c2;
                    if (col     > qi0) sa[nb][0] = -1e38f;
                    if (col + 1 > qi0) sa[nb][1] = -1e38f;
                    if (col     > qi1) sa[nb][2] = -1e38f;
                    if (col + 1 > qi1) sa[nb][3] = -1e38f;
                }
            }

            // ---- fixed-shift softmax ----
#pragma unroll
            for (int nb = 0; nb < 8; nb++) {
                sa[nb][0] = fexp2s(sa[nb][0]); l0 += sa[nb][0];
                sa[nb][1] = fexp2s(sa[nb][1]); l0 += sa[nb][1];
                sa[nb][2] = fexp2s(sa[nb][2]); l1 += sa[nb][2];
                sa[nb][3] = fexp2s(sa[nb][3]); l1 += sa[nb][3];
            }

            // ---- O += P V (4 k16-blocks) ----
#pragma unroll
            for (int jk = 0; jk < 4; jk++) {
                uint32_t ph[4], pl[4];
                split2(sa[2*jk][0],   sa[2*jk][1],   ph[0], pl[0]);
                split2(sa[2*jk][2],   sa[2*jk][3],   ph[1], pl[1]);
                split2(sa[2*jk+1][0], sa[2*jk+1][1], ph[2], pl[2]);
                split2(sa[2*jk+1][2], sa[2*jk+1][3], ph[3], pl[3]);
                uint32_t vhf[8][2], vlf[8][2];
#pragma unroll
                for (int g = 0; g < 4; g++) {
                    uint32_t off = (uint32_t)(((jk*16 + vRow) * LDQ + g*16 + vCol) * 2);
                    ldmatrix_x4_trans(vhf[2*g][0], vhf[2*g][1],
                                      vhf[2*g+1][0], vhf[2*g+1][1], uVh + off);
                    ldmatrix_x4_trans(vlf[2*g][0], vlf[2*g][1],
                                      vlf[2*g+1][0], vlf[2*g+1][1], uVl + off);
                }
#pragma unroll
                for (int nb = 0; nb < 8; nb++) mma_bf16(o[nb], ph, vhf[nb]);
#pragma unroll
                for (int nb = 0; nb < 8; nb++) mma_bf16(o[nb], ph, vlf[nb]);
#pragma unroll
                for (int nb = 0; nb < 8; nb++) mma_bf16(o[nb], pl, vhf[nb]);
            }
        }
        __syncthreads();
    }

    l0 += __shfl_xor_sync(0xffffffffu, l0, 1);
    l0 += __shfl_xor_sync(0xffffffffu, l0, 2);
    l1 += __shfl_xor_sync(0xffffffffu, l1, 1);
    l1 += __shfl_xor_sync(0xffffffffu, l1, 2);
    float i0 = __fdividef(1.f, l0), i1 = __fdividef(1.f, l1);
#pragma unroll
    for (int nb = 0; nb < 8; nb++) {
        size_t e0 = ((size_t)(b*SEQ + qi0) * DIM + h*HD + nb*8 + c2) >> 1;
        size_t e1 = ((size_t)(b*SEQ + qi1) * DIM + h*HD + nb*8 + c2) >> 1;
        uint32_t h0, lo0, h1, lo1;
        split2(o[nb][0] * i0, o[nb][1] * i0, h0, lo0);
        split2(o[nb][2] * i1, o[nb][3] * i1, h1, lo1);
        ((uint32_t*)Oh)[e0] = h0; ((uint32_t*)Ol)[e0] = lo0;
        ((uint32_t*)Oh)[e1] = h1; ((uint32_t*)Ol)[e1] = lo1;
    }
}

// =============================== Launch ====================================
extern "C" void kernel_launch(void* const* d_in, const int* in_sizes, int n_in,
                              void* d_out, int out_size)
{
    const float* x  = (const float*)d_in[0];
    const float* wq = (const float*)d_in[1];
    const float* wk = (const float*)d_in[2];
    const float* wv = (const float*)d_in[3];
    const float* wo = (const float*)d_in[4];
    float* out = (float*)d_out;

    __nv_bfloat16 *xh, *xl, *wqh, *wql, *wkh, *wkl, *wvh, *wvl, *woh, *wol;
    __nv_bfloat16 *Qh, *Ql, *Kh, *Kl, *Vh, *Vl, *Oh, *Ol;
    cudaGetSymbolAddress((void**)&xh,  g_xh);  cudaGetSymbolAddress((void**)&xl,  g_xl);
    cudaGetSymbolAddress((void**)&wqh, g_wqh); cudaGetSymbolAddress((void**)&wql, g_wql);
    cudaGetSymbolAddress((void**)&wkh, g_wkh); cudaGetSymbolAddress((void**)&wkl, g_wkl);
    cudaGetSymbolAddress((void**)&wvh, g_wvh); cudaGetSymbolAddress((void**)&wvl, g_wvl);
    cudaGetSymbolAddress((void**)&woh, g_woh); cudaGetSymbolAddress((void**)&wol, g_wol);
    cudaGetSymbolAddress((void**)&Qh,  g_Qh);  cudaGetSymbolAddress((void**)&Ql,  g_Ql);
    cudaGetSymbolAddress((void**)&Kh,  g_Kh);  cudaGetSymbolAddress((void**)&Kl,  g_Kl);
    cudaGetSymbolAddress((void**)&Vh,  g_Vh);  cudaGetSymbolAddress((void**)&Vl,  g_Vl);
    cudaGetSymbolAddress((void**)&Oh,  g_Oh);  cudaGetSymbolAddress((void**)&Ol,  g_Ol);

    cudaFuncSetAttribute(gemm_qkv, cudaFuncAttributeMaxDynamicSharedMemorySize, GEMM_SMEM);
    cudaFuncSetAttribute(gemm_o,   cudaFuncAttributeMaxDynamicSharedMemorySize, GEMM_SMEM);
    cudaFuncSetAttribute(attn_ps,  cudaFuncAttributeMaxDynamicSharedMemorySize, ATT_SMEM);

    split_all<<<(SPLIT_N4 + 511)/512, 256>>>(x, wq, wk, wv, wo,
        xh, xl, wqh, wql, wkh, wkl, wvh, wvl, woh, wol);

    gemm_qkv<<<dim3(24, MTOT/128), 256, GEMM_SMEM>>>(
        xh, xl, wqh, wql, wkh, wkl, wvh, wvl, Qh, Ql, Kh, Kl, Vh, Vl);
    attn_ps<<<dim3(SEQ/128, NH, BATCH), 256, ATT_SMEM>>>(
        Qh, Ql, Kh, Kl, Vh, Vl, Oh, Ol);
    gemm_o<<<dim3(DIM/128, MTOT/128), 256, GEMM_SMEM>>>(
        Oh, Ol, woh, wol, out);
}

// round 17
// speedup vs baseline: 1.0223x; 1.0223x over previous
#include <cuda_runtime.h>
#include <cuda_bf16.h>
#include <cstdint>
#include <math.h>

// Problem constants
#define BATCH 2
#define SEQ   2048
#define DIM   2048
#define NH    32
#define NKV   8
#define HD    64
#define KVD   (NKV*HD)    // 512
#define MTOT  (BATCH*SEQ) // 4096

// Scratch (device globals: allocation-free) — all pre-split bf16 pairs
__device__ __nv_bfloat16 g_xh [MTOT * DIM],  g_xl [MTOT * DIM];
__device__ __nv_bfloat16 g_wqh[DIM * DIM],   g_wql[DIM * DIM];
__device__ __nv_bfloat16 g_wkh[KVD * DIM],   g_wkl[KVD * DIM];
__device__ __nv_bfloat16 g_wvh[KVD * DIM],   g_wvl[KVD * DIM];
__device__ __nv_bfloat16 g_woh[DIM * DIM],   g_wol[DIM * DIM];
__device__ __nv_bfloat16 g_Qh [MTOT * DIM],  g_Ql [MTOT * DIM];
__device__ __nv_bfloat16 g_Kh [MTOT * KVD],  g_Kl [MTOT * KVD];
__device__ __nv_bfloat16 g_Vh [MTOT * KVD],  g_Vl [MTOT * KVD];
__device__ __nv_bfloat16 g_Oh [MTOT * DIM],  g_Ol [MTOT * DIM];

// ============================ helpers ======================================
__device__ __forceinline__ uint32_t smem_u32(const void* p) {
    uint32_t a;
    asm("{ .reg .u64 t; cvta.to.shared.u64 t, %1; cvt.u32.u64 %0, t; }"
        : "=r"(a) : "l"(p));
    return a;
}
__device__ __forceinline__ void cp16(uint32_t dst, const void* src) {
    asm volatile("cp.async.cg.shared.global [%0], [%1], 16;"
                 :: "r"(dst), "l"(src) : "memory");
}
#define CP_COMMIT() asm volatile("cp.async.commit_group;" ::: "memory")
#define CP_WAIT0()  asm volatile("cp.async.wait_group 0;" ::: "memory")
#define CP_WAIT1()  asm volatile("cp.async.wait_group 1;" ::: "memory")

__device__ __forceinline__ void ldmatrix_x4(uint32_t& r0, uint32_t& r1,
                                            uint32_t& r2, uint32_t& r3,
                                            uint32_t addr) {
    asm volatile("ldmatrix.sync.aligned.m8n8.x4.shared.b16 {%0,%1,%2,%3}, [%4];"
                 : "=r"(r0), "=r"(r1), "=r"(r2), "=r"(r3) : "r"(addr));
}
__device__ __forceinline__ void ldmatrix_x4_trans(uint32_t& r0, uint32_t& r1,
                                                  uint32_t& r2, uint32_t& r3,
                                                  uint32_t addr) {
    asm volatile("ldmatrix.sync.aligned.m8n8.x4.trans.shared.b16 {%0,%1,%2,%3}, [%4];"
                 : "=r"(r0), "=r"(r1), "=r"(r2), "=r"(r3) : "r"(addr));
}
__device__ __forceinline__ void mma_bf16(float* d, const uint32_t* a,
                                         const uint32_t* b) {
    asm volatile(
        "mma.sync.aligned.m16n8k16.row.col.f32.bf16.bf16.f32 "
        "{%0,%1,%2,%3}, {%4,%5,%6,%7}, {%8,%9}, {%0,%1,%2,%3};"
        : "+f"(d[0]), "+f"(d[1]), "+f"(d[2]), "+f"(d[3])
        : "r"(a[0]), "r"(a[1]), "r"(a[2]), "r"(a[3]), "r"(b[0]), "r"(b[1]));
}

// fp32 pair -> packed (hi,lo) bf16x2
__device__ __forceinline__ void split2(float a, float b, uint32_t& hi, uint32_t& lo) {
    __nv_bfloat16 ha = __float2bfloat16(a), hb = __float2bfloat16(b);
    hi = (uint32_t)__bfloat16_as_ushort(ha) |
         ((uint32_t)__bfloat16_as_ushort(hb) << 16);
    float ra = a - __bfloat162float(ha);
    float rb = b - __bfloat162float(hb);
    uint32_t d;
    asm("cvt.rn.bf16x2.f32 %0, %1, %2;" : "=r"(d) : "f"(rb), "f"(ra));
    lo = d;
}

// Fixed-shift softmax exponential: exp(s*0.125 - 46*ln2) = 2^(s*0.1803 - 46).
__device__ __forceinline__ float fexp2s(float x) {
    float y = fmaxf(fmaf(x, 0.1803368801f, -46.0f), -126.f);
    float r = rintf(y);
    float f = y - r;
    float p = 1.3333558e-3f;
    p = fmaf(p, f, 9.6181291e-3f);
    p = fmaf(p, f, 5.5504109e-2f);
    p = fmaf(p, f, 2.4022651e-1f);
    p = fmaf(p, f, 6.9314718e-1f);
    p = fmaf(p, f, 1.0f);
    return p * __int_as_float(((int)r + 127) << 23);
}

// XOR swizzle for 64B-wide rows (bijective; store & load use same map)
__device__ __forceinline__ uint32_t swz(uint32_t off) {
    return off ^ (((off >> 6) & 7u) << 4);
}

// ================ fused pre-split kernel (fp32 -> hi/lo bf16) ==============
// 2 float4 per thread (MLP=2), halved grid.
#define SPLIT_N4 4718592
__global__ __launch_bounds__(256)
void split_all(const float* __restrict__ x,  const float* __restrict__ wq,
               const float* __restrict__ wk, const float* __restrict__ wv,
               const float* __restrict__ wo,
               __nv_bfloat16* xh,  __nv_bfloat16* xl,
               __nv_bfloat16* wqh, __nv_bfloat16* wql,
               __nv_bfloat16* wkh, __nv_bfloat16* wkl,
               __nv_bfloat16* wvh, __nv_bfloat16* wvl,
               __nv_bfloat16* woh, __nv_bfloat16* wol)
{
    int base = blockIdx.x * 512 + threadIdx.x;
#pragma unroll
    for (int u = 0; u < 2; u++) {
        int i = base + u * 256;
        if (i >= SPLIT_N4) return;
        const float* in; __nv_bfloat16 *hi, *lo; int off;
        if (i < 2097152)      { in = x;  hi = xh;  lo = xl;  off = 0; }
        else if (i < 3145728) { in = wq; hi = wqh; lo = wql; off = 2097152; }
        else if (i < 3407872) { in = wk; hi = wkh; lo = wkl; off = 3145728; }
        else if (i < 3670016) { in = wv; hi = wvh; lo = wvl; off = 3407872; }
        else                  { in = wo; hi = woh; lo = wol; off = 3670016; }
        int k = i - off;
        float4 v = ((const float4*)in)[k];
        uint32_t h0, l0, h1, l1;
        split2(v.x, v.y, h0, l0);
        split2(v.z, v.w, h1, l1);
        ((uint2*)hi)[k] = make_uint2(h0, h1);
        ((uint2*)lo)[k] = make_uint2(l0, l1);
    }
}

// ============== pre-split bf16 GEMM: swizzled 3-stage (round-8 config) =====
#define GSTG 32768
#define GEMM_SMEM (3 * GSTG)   // 98304 bytes

template<int SPLIT>
__device__ __forceinline__ void gemm_tile(
    const __nv_bfloat16* __restrict__ Ah_t, const __nv_bfloat16* __restrict__ Al_t,
    const __nv_bfloat16* __restrict__ Bh_t, const __nv_bfloat16* __restrict__ Bl_t,
    float* __restrict__ C, __nv_bfloat16* __restrict__ Ch,
    __nv_bfloat16* __restrict__ Cl, int ldc, int K, __nv_bfloat16* gsm)
{
    const uint32_t usm = smem_u32(gsm);
    const int tid  = threadIdx.x;
    const int lane = tid & 31;
    const int wid  = tid >> 5;
    const int wm   = wid & 1;
    const int wn   = wid >> 1;

    const __nv_bfloat16* srcs[4] = { Ah_t, Al_t, Bh_t, Bl_t };

    float acc[4][4][4];
#pragma unroll
    for (int i = 0; i < 4; i++)
#pragma unroll
        for (int j = 0; j < 4; j++)
#pragma unroll
            for (int q = 0; q < 4; q++) acc[i][j][q] = 0.f;

    const int aRow = wm * 64 + (lane & 15);
    const int aCol = (lane >> 4) << 4;                 // bytes
    const int bRow = wn * 32 + ((lane >> 4) << 3) + (lane & 7);
    const int bCol = ((lane >> 3) & 1) << 4;           // bytes

    const int NC = K / 32;

    auto issue = [&](int k0, uint32_t base) {
#pragma unroll
        for (int j = 0; j < 8; j++) {
            int s   = tid + (j << 8);
            int arr = s >> 9;
            int w5  = s & 511;
            int r   = w5 >> 2;
            int c8  = w5 & 3;
            cp16(base + (uint32_t)(arr * 8192) + swz((uint32_t)(r * 64 + c8 * 16)),
                 srcs[arr] + (size_t)r * K + k0 + c8 * 8);
        }
    };

    issue(0, usm);         CP_COMMIT();
    issue(32, usm + GSTG); CP_COMMIT();

    for (int c = 0; c < NC; c++) {
        CP_WAIT1();
        __syncthreads();
        if (c + 2 < NC)
            issue((c + 2) * 32, usm + (uint32_t)(((c + 2) % 3) * GSTG));
        CP_COMMIT();

        const uint32_t sb = usm + (uint32_t)((c % 3) * GSTG);
#pragma unroll
        for (int kk = 0; kk < 2; kk++) {
            const int kc = kk * 32;
            uint32_t bh[4][2], bl[4][2];
#pragma unroll
            for (int g = 0; g < 2; g++) {
                uint32_t off = swz((uint32_t)((bRow + g * 16) * 64 + bCol + kc));
                ldmatrix_x4(bh[g*2][0], bh[g*2][1], bh[g*2+1][0], bh[g*2+1][1],
                            sb + 16384 + off);
                ldmatrix_x4(bl[g*2][0], bl[g*2][1], bl[g*2+1][0], bl[g*2+1][1],
                            sb + 24576 + off);
            }
#pragma unroll
            for (int mi = 0; mi < 4; mi++) {
                uint32_t ah[4], al[4];
                uint32_t off = swz((uint32_t)((aRow + mi * 16) * 64 + aCol + kc));
                ldmatrix_x4(ah[0], ah[1], ah[2], ah[3], sb + off);
                ldmatrix_x4(al[0], al[1], al[2], al[3], sb + 8192 + off);
#pragma unroll
                for (int ni = 0; ni < 4; ni++) mma_bf16(acc[mi][ni], ah, bh[ni]);
#pragma unroll
                for (int ni = 0; ni < 4; ni++) mma_bf16(acc[mi][ni], ah, bl[ni]);
#pragma unroll
                for (int ni = 0; ni < 4; ni++) mma_bf16(acc[mi][ni], al, bh[ni]);
            }
        }
    }

    const int erow = lane >> 2;
    const int ecol = (lane & 3) << 1;
#pragma unroll
    for (int mi = 0; mi < 4; mi++) {
#pragma unroll
        for (int ni = 0; ni < 4; ni++) {
            int r0 = wm * 64 + mi * 16 + erow;
            int cc = wn * 32 + ni * 8 + ecol;
            if (SPLIT) {
                uint32_t h0, l0, h1, l1;
                split2(acc[mi][ni][0], acc[mi][ni][1], h0, l0);
                split2(acc[mi][ni][2], acc[mi][ni][3], h1, l1);
                size_t i0 = ((size_t)r0 * ldc + cc) >> 1;
                size_t i1 = ((size_t)(r0 + 8) * ldc + cc) >> 1;
                ((uint32_t*)Ch)[i0] = h0; ((uint32_t*)Cl)[i0] = l0;
                ((uint32_t*)Ch)[i1] = h1; ((uint32_t*)Cl)[i1] = l1;
            } else {
                *(float2*)&C[(size_t)r0 * ldc + cc] =
                    make_float2(acc[mi][ni][0], acc[mi][ni][1]);
                *(float2*)&C[(size_t)(r0 + 8) * ldc + cc] =
                    make_float2(acc[mi][ni][2], acc[mi][ni][3]);
            }
        }
    }
}

// Fused Q/K/V projection: grid.x = 24 n-tiles (16 Q | 4 K | 4 V)
__global__ __launch_bounds__(256, 2)
void gemm_qkv(const __nv_bfloat16* __restrict__ xh, const __nv_bfloat16* __restrict__ xl,
              const __nv_bfloat16* __restrict__ wqh, const __nv_bfloat16* __restrict__ wql,
              const __nv_bfloat16* __restrict__ wkh, const __nv_bfloat16* __restrict__ wkl,
              const __nv_bfloat16* __restrict__ wvh, const __nv_bfloat16* __restrict__ wvl,
              __nv_bfloat16* __restrict__ Qh, __nv_bfloat16* __restrict__ Ql,
              __nv_bfloat16* __restrict__ Kh, __nv_bfloat16* __restrict__ Kl,
              __nv_bfloat16* __restrict__ Vh, __nv_bfloat16* __restrict__ Vl)
{
    extern __shared__ __nv_bfloat16 gsm[];
    const int nt = blockIdx.x;
    const int bm = blockIdx.y * 128;
    const __nv_bfloat16 *Bh, *Bl;
    __nv_bfloat16 *Ch, *Cl;
    int ldc, bn;
    if (nt < 16)      { Bh = wqh; Bl = wql; Ch = Qh; Cl = Ql; ldc = DIM; bn = nt * 128; }
    else if (nt < 20) { Bh = wkh; Bl = wkl; Ch = Kh; Cl = Kl; ldc = KVD; bn = (nt - 16) * 128; }
    else              { Bh = wvh; Bl = wvl; Ch = Vh; Cl = Vl; ldc = KVD; bn = (nt - 20) * 128; }
    gemm_tile<1>(xh + (size_t)bm * DIM, xl + (size_t)bm * DIM,
                 Bh + (size_t)bn * DIM, Bl + (size_t)bn * DIM,
                 nullptr,
                 Ch + (size_t)bm * ldc + bn, Cl + (size_t)bm * ldc + bn,
                 ldc, DIM, gsm);
}

__global__ __launch_bounds__(256, 2)
void gemm_o(const __nv_bfloat16* __restrict__ Ah, const __nv_bfloat16* __restrict__ Al,
            const __nv_bfloat16* __restrict__ Bh, const __nv_bfloat16* __restrict__ Bl,
            float* __restrict__ C)
{
    extern __shared__ __nv_bfloat16 gsm[];
    const int bm = blockIdx.y * 128, bn = blockIdx.x * 128;
    gemm_tile<0>(Ah + (size_t)bm * DIM, Al + (size_t)bm * DIM,
                 Bh + (size_t)bn * DIM, Bl + (size_t)bn * DIM,
                 C + (size_t)bm * DIM + bn, nullptr, nullptr,
                 DIM, DIM, gsm);
}

// ===== Flash attention: 128x128 tiles, FIXED-SHIFT softmax (round-10 body) =
#define LDQ 72
#define AKV2  36864
#define ATT_SMEM ((18432 + 2 * AKV2) * 2)   // 184320 bytes

__global__ __launch_bounds__(256, 1)
void attn_ps(const __nv_bfloat16* __restrict__ Qh_g, const __nv_bfloat16* __restrict__ Ql_g,
             const __nv_bfloat16* __restrict__ Kh_g, const __nv_bfloat16* __restrict__ Kl_g,
             const __nv_bfloat16* __restrict__ Vh_g, const __nv_bfloat16* __restrict__ Vl_g,
             __nv_bfloat16* __restrict__ Oh, __nv_bfloat16* __restrict__ Ol)
{
    extern __shared__ __nv_bfloat16 sm[];
    const uint32_t usm = smem_u32(sm);

    const int b = blockIdx.z, h = blockIdx.y;
    const int qt = (int)gridDim.x - 1 - (int)blockIdx.x;
    const int tid = threadIdx.x, lane = tid & 31, w = tid >> 5;
    const int kvh = h >> 2;
    const int qBase = qt * 128;
    const int wq0 = qBase + 16 * w;

    const __nv_bfloat16* kvsrc[4] = {
        Kh_g + (size_t)(b * SEQ) * KVD + kvh * HD,
        Kl_g + (size_t)(b * SEQ) * KVD + kvh * HD,
        Vh_g + (size_t)(b * SEQ) * KVD + kvh * HD,
        Vl_g + (size_t)(b * SEQ) * KVD + kvh * HD };

    {
        const __nv_bfloat16* qs[2] = {
            Qh_g + (size_t)(b * SEQ + qBase) * DIM + h * HD,
            Ql_g + (size_t)(b * SEQ + qBase) * DIM + h * HD };
#pragma unroll
        for (int j = 0; j < 8; j++) {
            int s = tid + (j << 8);
            int arr = s >> 10, r = (s >> 3) & 127, c = s & 7;
            cp16(usm + (uint32_t)((arr * 9216 + r * LDQ + c * 8) * 2),
                 qs[arr] + (size_t)r * DIM + c * 8);
        }
        CP_COMMIT();
    }

    auto issue_kv = [&](int j, int st) {
        int kvBase = j * 128;
        uint32_t base = usm + (uint32_t)((18432 + st * AKV2) * 2);
#pragma unroll
        for (int q = 0; q < 16; q++) {
            int s = tid + (q << 8);
            int arr = s >> 10, r = (s >> 3) & 127, c = s & 7;
            cp16(base + (uint32_t)((arr * 9216 + r * LDQ + c * 8) * 2),
                 kvsrc[arr] + (size_t)(kvBase + r) * KVD + c * 8);
        }
    };

    const int ntiles = qt + 1;
    issue_kv(0, 0);
    CP_COMMIT();

    CP_WAIT1();
    __syncthreads();

    uint32_t qh[4][4], ql[4][4];
    {
        int off0 = (16*w + (lane & 15)) * LDQ + ((lane >> 4) << 3);
#pragma unroll
        for (int kb = 0; kb < 4; kb++) {
            uint32_t off = (uint32_t)((off0 + kb * 16) * 2);
            ldmatrix_x4(qh[kb][0], qh[kb][1], qh[kb][2], qh[kb][3], usm + off);
            ldmatrix_x4(ql[kb][0], ql[kb][1], ql[kb][2], ql[kb][3],
                        usm + (uint32_t)(9216 * 2) + off);
        }
    }

    float o[8][4];
#pragma unroll
    for (int nb = 0; nb < 8; nb++)
#pragma unroll
        for (int q = 0; q < 4; q++) o[nb][q] = 0.f;
    float l0 = 0.f, l1 = 0.f;

    const int bN = ((lane >> 4) << 3) + (lane & 7);
    const int bK = ((lane >> 3) & 1) << 3;
    const int vRow = lane & 15, vCol = (lane >> 4) << 3;
    const int r0   = lane >> 2;
    const int c2   = (lane & 3) << 1;
    const int qi0  = wq0 + r0, qi1 = qi0 + 8;

    for (int j = 0; j < ntiles; j++) {
        const int kvBase = j * 128;
        const int st = j & 1;
        if (j + 1 < ntiles) {
            issue_kv(j + 1, st ^ 1);
            CP_COMMIT();
            CP_WAIT1();
        } else {
            CP_WAIT0();
        }
        __syncthreads();

        if (kvBase <= wq0 + 15) {
            const uint32_t kvb = usm + (uint32_t)((18432 + st * AKV2) * 2);
            const uint32_t uKh = kvb, uKl = kvb + 9216 * 2;
            const uint32_t uVh = kvb + 18432 * 2, uVl = kvb + 27648 * 2;

            float sa[16][4];
#pragma unroll
            for (int nb = 0; nb < 16; nb++)
#pragma unroll
                for (int q = 0; q < 4; q++) sa[nb][q] = 0.f;

#pragma unroll
            for (int hf = 0; hf < 2; hf++) {
#pragma unroll
                for (int kb = 0; kb < 4; kb++) {
                    uint32_t bhf[8][2], blf[8][2];
#pragma unroll
                    for (int g = 0; g < 4; g++) {
                        uint32_t off = (uint32_t)((((hf*64 + g*16) + bN) * LDQ
                                                  + kb*16 + bK) * 2);
                        ldmatrix_x4(bhf[2*g][0], bhf[2*g][1],
                                    bhf[2*g+1][0], bhf[2*g+1][1], uKh + off);
                        ldmatrix_x4(blf[2*g][0], blf[2*g][1],
                                    blf[2*g+1][0], blf[2*g+1][1], uKl + off);
                    }
                    float* sp = &sa[hf*8][0];
#pragma unroll
                    for (int nb = 0; nb < 8; nb++) mma_bf16(sp + nb*4, qh[kb], bhf[nb]);
#pragma unroll
                    for (int nb = 0; nb < 8; nb++) mma_bf16(sp + nb*4, qh[kb], blf[nb]);
#pragma unroll
                    for (int nb = 0; nb < 8; nb++) mma_bf16(sp + nb*4, ql[kb], bhf[nb]);
                }
            }

            // causal mask (boundary tile only)
            if (kvBase + 127 > wq0) {
#pragma unroll
                for (int nb = 0; nb < 16; nb++) {
                    int col = kvBase + nb * 8 + c2;
                    if (col     > qi0) sa[nb][0] = -1e38f;
                    if (col + 1 > qi0) sa[nb][1] = -1e38f;
                    if (col     > qi1) sa[nb][2] = -1e38f;
                    if (col + 1 > qi1) sa[nb][3] = -1e38f;
                }
            }

            // fixed-shift softmax
#pragma unroll
            for (int nb = 0; nb < 16; nb++) {
                sa[nb][0] = fexp2s(sa[nb][0]); l0 += sa[nb][0];
                sa[nb][1] = fexp2s(sa[nb][1]); l0 += sa[nb][1];
                sa[nb][2] = fexp2s(sa[nb][2]); l1 += sa[nb][2];
                sa[nb][3] = fexp2s(sa[nb][3]); l1 += sa[nb][3];
            }

            // O += P V
#pragma unroll
            for (int jk = 0; jk < 8; jk++) {
                uint32_t ph[4], pl[4];
                split2(sa[2*jk][0],   sa[2*jk][1],   ph[0], pl[0]);
                split2(sa[2*jk][2],   sa[2*jk][3],   ph[1], pl[1]);
                split2(sa[2*jk+1][0], sa[2*jk+1][1], ph[2], pl[2]);
                split2(sa[2*jk+1][2], sa[2*jk+1][3], ph[3], pl[3]);
                uint32_t vhf[8][2], vlf[8][2];
#pragma unroll
                for (int g = 0; g < 4; g++) {
                    uint32_t off = (uint32_t)(((jk*16 + vRow) * LDQ + g*16 + vCol) * 2);
                    ldmatrix_x4_trans(vhf[2*g][0], vhf[2*g][1],
                                      vhf[2*g+1][0], vhf[2*g+1][1], uVh + off);
                    ldmatrix_x4_trans(vlf[2*g][0], vlf[2*g][1],
                                      vlf[2*g+1][0], vlf[2*g+1][1], uVl + off);
                }
#pragma unroll
                for (int nb = 0; nb < 8; nb++) mma_bf16(o[nb], ph, vhf[nb]);
#pragma unroll
                for (int nb = 0; nb < 8; nb++) mma_bf16(o[nb], ph, vlf[nb]);
#pragma unroll
                for (int nb = 0; nb < 8; nb++) mma_bf16(o[nb], pl, vhf[nb]);
            }
        }
        __syncthreads();
    }

    l0 += __shfl_xor_sync(0xffffffffu, l0, 1);
    l0 += __shfl_xor_sync(0xffffffffu, l0, 2);
    l1 += __shfl_xor_sync(0xffffffffu, l1, 1);
    l1 += __shfl_xor_sync(0xffffffffu, l1, 2);
    float i0 = __fdividef(1.f, l0), i1 = __fdividef(1.f, l1);
#pragma unroll
    for (int nb = 0; nb < 8; nb++) {
        size_t e0 = ((size_t)(b*SEQ + qi0) * DIM + h*HD + nb*8 + c2) >> 1;
        size_t e1 = ((size_t)(b*SEQ + qi1) * DIM + h*HD + nb*8 + c2) >> 1;
        uint32_t h0, lo0, h1, lo1;
        split2(o[nb][0] * i0, o[nb][1] * i0, h0, lo0);
        split2(o[nb][2] * i1, o[nb][3] * i1, h1, lo1);
        ((uint32_t*)Oh)[e0] = h0; ((uint32_t*)Ol)[e0] = lo0;
        ((uint32_t*)Oh)[e1] = h1; ((uint32_t*)Ol)[e1] = lo1;
    }
}

// =============================== Launch ====================================
extern "C" void kernel_launch(void* const* d_in, const int* in_sizes, int n_in,
                              void* d_out, int out_size)
{
    const float* x  = (const float*)d_in[0];
    const float* wq = (const float*)d_in[1];
    const float* wk = (const float*)d_in[2];
    const float* wv = (const float*)d_in[3];
    const float* wo = (const float*)d_in[4];
    float* out = (float*)d_out;

    __nv_bfloat16 *xh, *xl, *wqh, *wql, *wkh, *wkl, *wvh, *wvl, *woh, *wol;
    __nv_bfloat16 *Qh, *Ql, *Kh, *Kl, *Vh, *Vl, *Oh, *Ol;
    cudaGetSymbolAddress((void**)&xh,  g_xh);  cudaGetSymbolAddress((void**)&xl,  g_xl);
    cudaGetSymbolAddress((void**)&wqh, g_wqh); cudaGetSymbolAddress((void**)&wql, g_wql);
    cudaGetSymbolAddress((void**)&wkh, g_wkh); cudaGetSymbolAddress((void**)&wkl, g_wkl);
    cudaGetSymbolAddress((void**)&wvh, g_wvh); cudaGetSymbolAddress((void**)&wvl, g_wvl);
    cudaGetSymbolAddress((void**)&woh, g_woh); cudaGetSymbolAddress((void**)&wol, g_wol);
    cudaGetSymbolAddress((void**)&Qh,  g_Qh);  cudaGetSymbolAddress((void**)&Ql,  g_Ql);
    cudaGetSymbolAddress((void**)&Kh,  g_Kh);  cudaGetSymbolAddress((void**)&Kl,  g_Kl);
    cudaGetSymbolAddress((void**)&Vh,  g_Vh);  cudaGetSymbolAddress((void**)&Vl,  g_Vl);
    cudaGetSymbolAddress((void**)&Oh,  g_Oh);  cudaGetSymbolAddress((void**)&Ol,  g_Ol);

    cudaFuncSetAttribute(gemm_qkv, cudaFuncAttributeMaxDynamicSharedMemorySize, GEMM_SMEM);
    cudaFuncSetAttribute(gemm_o,   cudaFuncAttributeMaxDynamicSharedMemorySize, GEMM_SMEM);
    cudaFuncSetAttribute(attn_ps,  cudaFuncAttributeMaxDynamicSharedMemorySize, ATT_SMEM);

    split_all<<<(SPLIT_N4 + 511)/512, 256>>>(x, wq, wk, wv, wo,
        xh, xl, wqh, wql, wkh, wkl, wvh, wvl, woh, wol);

    gemm_qkv<<<dim3(24, MTOT/128), 256, GEMM_SMEM>>>(
        xh, xl, wqh, wql, wkh, wkl, wvh, wvl, Qh, Ql, Kh, Kl, Vh, Vl);
    attn_ps<<<dim3(SEQ/128, NH, BATCH), 256, ATT_SMEM>>>(
        Qh, Ql, Kh, Kl, Vh, Vl, Oh, Ol);
    gemm_o<<<dim3(DIM/128, MTOT/128), 256, GEMM_SMEM>>>(
        Oh, Ol, woh, wol, out);
}